// round 1
// baseline (speedup 1.0000x reference)
#include <cuda_runtime.h>
#include <cuda_bf16.h>

// Problem constants (match reference)
#define SIZE   16384      // 128*128
#define KNN    16
#define ND     5          // num derivatives (order 2, 2D)

// Inputs (metadata order):
//  0: x          [B, SIZE]        f32
//  1: points     [B, SIZE, 2]     f32
//  2: edge_index [B, SIZE*K]      i32
//  3: dt         scalar           f32
//  4: dist       [B, SIZE, K]     f32
//  5: weight     [1,1,5]          f32
// out: [B, SIZE] f32

__global__ void __launch_bounds__(256)
tp_layer_kernel(const float* __restrict__ x,
                const float* __restrict__ points,
                const int*   __restrict__ edge_index,
                const float* __restrict__ dt_p,
                const float* __restrict__ dist,
                const float* __restrict__ weight,
                float* __restrict__ out,
                int total)   // B*SIZE
{
    int gid = blockIdx.x * blockDim.x + threadIdx.x;
    if (gid >= total) return;

    const int b = gid >> 14;          // / SIZE
    const int s = gid & (SIZE - 1);   // % SIZE

    const float* pts_b = points + (size_t)b * SIZE * 2;
    const float* x_b   = x + (size_t)b * SIZE;

    // center point + value
    const float2 pc = *reinterpret_cast<const float2*>(pts_b + 2 * s);
    const float  vc = x_b[s];

    // vectorized neighbor index / distance streams (16 = 4 x vec4)
    const int4*   ei4 = reinterpret_cast<const int4*>(edge_index + (size_t)b * SIZE * KNN + (size_t)s * KNN);
    const float4* dw4 = reinterpret_cast<const float4*>(dist       + (size_t)b * SIZE * KNN + (size_t)s * KNN);

    // symmetric 5x5 accumulators (upper triangle) + rhs
    float s00=0,s01=0,s02=0,s03=0,s04=0;
    float       s11=0,s12=0,s13=0,s14=0;
    float             s22=0,s23=0,s24=0;
    float                   s33=0,s34=0;
    float                         s44=0;
    float t0=0,t1=0,t2=0,t3=0,t4=0;

    #pragma unroll
    for (int g = 0; g < 4; ++g) {
        const int4   ei = ei4[g];
        const float4 dw = dw4[g];
        const int   idx[4] = {ei.x, ei.y, ei.z, ei.w};
        const float wts[4] = {dw.x, dw.y, dw.z, dw.w};

        #pragma unroll
        for (int j = 0; j < 4; ++j) {
            const int    id = idx[j];
            const float  w  = wts[j];
            const float2 pn = *reinterpret_cast<const float2*>(pts_b + 2 * id);
            const float  vn = x_b[id];

            const float dx = pn.x - pc.x;
            const float dy = pn.y - pc.y;

            // weighted Taylor design row
            const float a0 = dx * w;
            const float a1 = dy * w;
            const float a2 = 0.5f * dx * dx * w;
            const float a3 = dx * dy * w;
            const float a4 = 0.5f * dy * dy * w;
            const float r  = (vn - vc) * w;

            s00 += a0*a0; s01 += a0*a1; s02 += a0*a2; s03 += a0*a3; s04 += a0*a4;
                          s11 += a1*a1; s12 += a1*a2; s13 += a1*a3; s14 += a1*a4;
                                        s22 += a2*a2; s23 += a2*a3; s24 += a2*a4;
                                                      s33 += a3*a3; s34 += a3*a4;
                                                                    s44 += a4*a4;
            t0 += a0*r; t1 += a1*r; t2 += a2*r; t3 += a3*r; t4 += a4*r;
        }
    }

    // Assemble full matrix + ridge, augmented RHS; Gaussian elimination
    // (SPD + ridge -> no pivoting required).
    const float RIDGE = 1e-6f;
    float m[ND][ND];
    m[0][0]=s00+RIDGE; m[0][1]=s01; m[0][2]=s02; m[0][3]=s03; m[0][4]=s04;
    m[1][0]=s01; m[1][1]=s11+RIDGE; m[1][2]=s12; m[1][3]=s13; m[1][4]=s14;
    m[2][0]=s02; m[2][1]=s12; m[2][2]=s22+RIDGE; m[2][3]=s23; m[2][4]=s24;
    m[3][0]=s03; m[3][1]=s13; m[3][2]=s23; m[3][3]=s33+RIDGE; m[3][4]=s34;
    m[4][0]=s04; m[4][1]=s14; m[4][2]=s24; m[4][3]=s34; m[4][4]=s44+RIDGE;
    float bv[ND] = {t0, t1, t2, t3, t4};

    #pragma unroll
    for (int i = 0; i < ND; ++i) {
        const float inv = __frcp_rn(m[i][i]);
        #pragma unroll
        for (int r2 = 0; r2 < ND; ++r2) {
            if (r2 > i) {
                const float f = m[r2][i] * inv;
                #pragma unroll
                for (int c = 0; c < ND; ++c) {
                    if (c >= i) m[r2][c] -= f * m[i][c];
                }
                bv[r2] -= f * bv[i];
            }
        }
    }
    // back substitution
    float sol[ND];
    #pragma unroll
    for (int i = ND - 1; i >= 0; --i) {
        float acc = bv[i];
        #pragma unroll
        for (int c = 0; c < ND; ++c) {
            if (c > i) acc -= m[i][c] * sol[c];
        }
        sol[i] = acc * __frcp_rn(m[i][i]);
    }

    const float du = sol[0]*weight[0] + sol[1]*weight[1] + sol[2]*weight[2]
                   + sol[3]*weight[3] + sol[4]*weight[4];

    out[gid] = vc + dt_p[0] * du;
}

extern "C" void kernel_launch(void* const* d_in, const int* in_sizes, int n_in,
                              void* d_out, int out_size)
{
    const float* x      = (const float*)d_in[0];
    const float* points = (const float*)d_in[1];
    const int*   eidx   = (const int*)  d_in[2];
    const float* dt     = (const float*)d_in[3];
    const float* dist   = (const float*)d_in[4];
    const float* weight = (const float*)d_in[5];
    float* out = (float*)d_out;

    const int total = out_size;   // B * SIZE
    const int threads = 256;
    const int blocks = (total + threads - 1) / threads;
    tp_layer_kernel<<<blocks, threads>>>(x, points, eidx, dt, dist, weight, out, total);
}

// round 4
// speedup vs baseline: 1.8718x; 1.8718x over previous
#include <cuda_runtime.h>
#include <cuda_bf16.h>

// Problem constants (match reference)
#define SIZE     16384      // 128*128 points per batch
#define KNN      16
#define ND       5          // num derivatives (order 2, 2D)
#define NBATCH   32
#define CHUNKS   8          // CTAs per batch (smem kernel)
#define CTA_PTS  (SIZE / CHUNKS)   // 2048 points per CTA
#define NTHREADS 1024
#define PTS_PER_THREAD (CTA_PTS / NTHREADS)  // 2

// Dynamic smem: three scalar arrays px[SIZE], py[SIZE], sv[SIZE] (SoA: all 32
// banks hit uniformly by random gathers, unlike float2 which lands on even
// banks only).
#define SMEM_BYTES (3 * SIZE * sizeof(float))   // 196608

// ---------------------------------------------------------------------------
// Shared solve: accumulate normal equations from (dx,dy,w,r) rows and return du
// ---------------------------------------------------------------------------
struct Accum {
    float s00,s01,s02,s03,s04, s11,s12,s13,s14, s22,s23,s24, s33,s34, s44;
    float t0,t1,t2,t3,t4;
    __device__ __forceinline__ void init() {
        s00=s01=s02=s03=s04=s11=s12=s13=s14=s22=s23=s24=s33=s34=s44=0.f;
        t0=t1=t2=t3=t4=0.f;
    }
    __device__ __forceinline__ void add(float dx, float dy, float w, float r0) {
        const float a0 = dx * w;
        const float a1 = dy * w;
        const float a2 = 0.5f * dx * dx * w;
        const float a3 = dx * dy * w;
        const float a4 = 0.5f * dy * dy * w;
        const float r  = r0 * w;
        s00 += a0*a0; s01 += a0*a1; s02 += a0*a2; s03 += a0*a3; s04 += a0*a4;
                      s11 += a1*a1; s12 += a1*a2; s13 += a1*a3; s14 += a1*a4;
                                    s22 += a2*a2; s23 += a2*a3; s24 += a2*a4;
                                                  s33 += a3*a3; s34 += a3*a4;
                                                                s44 += a4*a4;
        t0 += a0*r; t1 += a1*r; t2 += a2*r; t3 += a3*r; t4 += a4*r;
    }
};

__device__ __forceinline__ float solve_and_dot(const Accum& A,
                                               const float* __restrict__ weight)
{
    const float RIDGE = 1e-6f;
    float m[ND][ND];
    m[0][0]=A.s00+RIDGE; m[0][1]=A.s01; m[0][2]=A.s02; m[0][3]=A.s03; m[0][4]=A.s04;
    m[1][0]=A.s01; m[1][1]=A.s11+RIDGE; m[1][2]=A.s12; m[1][3]=A.s13; m[1][4]=A.s14;
    m[2][0]=A.s02; m[2][1]=A.s12; m[2][2]=A.s22+RIDGE; m[2][3]=A.s23; m[2][4]=A.s24;
    m[3][0]=A.s03; m[3][1]=A.s13; m[3][2]=A.s23; m[3][3]=A.s33+RIDGE; m[3][4]=A.s34;
    m[4][0]=A.s04; m[4][1]=A.s14; m[4][2]=A.s24; m[4][3]=A.s34; m[4][4]=A.s44+RIDGE;
    float bv[ND] = {A.t0, A.t1, A.t2, A.t3, A.t4};

    #pragma unroll
    for (int i = 0; i < ND; ++i) {
        const float inv = __frcp_rn(m[i][i]);
        #pragma unroll
        for (int r2 = 0; r2 < ND; ++r2) {
            if (r2 > i) {
                const float f = m[r2][i] * inv;
                #pragma unroll
                for (int c = 0; c < ND; ++c)
                    if (c >= i) m[r2][c] -= f * m[i][c];
                bv[r2] -= f * bv[i];
            }
        }
    }
    float sol[ND];
    #pragma unroll
    for (int i = ND - 1; i >= 0; --i) {
        float acc = bv[i];
        #pragma unroll
        for (int c = 0; c < ND; ++c)
            if (c > i) acc -= m[i][c] * sol[c];
        sol[i] = acc * __frcp_rn(m[i][i]);
    }
    return sol[0]*weight[0] + sol[1]*weight[1] + sol[2]*weight[2]
         + sol[3]*weight[3] + sol[4]*weight[4];
}

// ---------------------------------------------------------------------------
// Primary kernel: full batch staged in 192 KB smem (SoA), gathers via LDS
// ---------------------------------------------------------------------------
__global__ void __launch_bounds__(NTHREADS, 1)
tp_layer_smem_kernel(const float* __restrict__ x,
                     const float* __restrict__ points,
                     const int*   __restrict__ edge_index,
                     const float* __restrict__ dt_p,
                     const float* __restrict__ dist,
                     const float* __restrict__ weight,
                     float* __restrict__ out)
{
    extern __shared__ float smem[];
    float* px = smem;
    float* py = smem + SIZE;
    float* sv = smem + 2 * SIZE;

    const int b     = blockIdx.x / CHUNKS;
    const int chunk = blockIdx.x % CHUNKS;
    const int tid   = threadIdx.x;

    const float* pts_b = points + (size_t)b * SIZE * 2;
    const float* x_b   = x + (size_t)b * SIZE;

    // Stage: coalesced float4 global reads, de-interleave into SoA smem.
    {
        const float4* srcp = reinterpret_cast<const float4*>(pts_b);
        #pragma unroll
        for (int i = 0; i < (SIZE / 2) / NTHREADS; ++i) {      // 8 iters
            const int k = tid + i * NTHREADS;                  // float4 = 2 points
            const float4 f = srcp[k];
            px[2*k]   = f.x;  py[2*k]   = f.y;
            px[2*k+1] = f.z;  py[2*k+1] = f.w;
        }
        const float4* srcx = reinterpret_cast<const float4*>(x_b);
        #pragma unroll
        for (int i = 0; i < (SIZE / 4) / NTHREADS; ++i) {      // 4 iters
            const int k = tid + i * NTHREADS;
            const float4 f = srcx[k];
            sv[4*k] = f.x; sv[4*k+1] = f.y; sv[4*k+2] = f.z; sv[4*k+3] = f.w;
        }
    }
    __syncthreads();

    const float dt = dt_p[0];
    const int s_base = chunk * CTA_PTS;
    const int*   eidx_g = edge_index + (size_t)b * SIZE * KNN;
    const float* dist_g = dist       + (size_t)b * SIZE * KNN;

    #pragma unroll
    for (int p = 0; p < PTS_PER_THREAD; ++p) {
        const int s = s_base + tid + p * NTHREADS;

        const float pcx = px[s], pcy = py[s], vc = sv[s];
        const int4*   ei4 = reinterpret_cast<const int4*>(eidx_g + (size_t)s * KNN);
        const float4* dw4 = reinterpret_cast<const float4*>(dist_g + (size_t)s * KNN);

        Accum A; A.init();
        #pragma unroll
        for (int g = 0; g < 4; ++g) {
            const int4   ei = ei4[g];
            const float4 dw = dw4[g];
            const int   idx[4] = {ei.x, ei.y, ei.z, ei.w};
            const float wts[4] = {dw.x, dw.y, dw.z, dw.w};
            #pragma unroll
            for (int j = 0; j < 4; ++j) {
                const int id = idx[j];
                A.add(px[id] - pcx, py[id] - pcy, wts[j], sv[id] - vc);
            }
        }
        const float du = solve_and_dot(A, weight);
        out[(size_t)b * SIZE + s] = vc + dt * du;
    }
}

// ---------------------------------------------------------------------------
// Fallback kernel (R1, known-good): global-memory gathers, no opt-in smem
// ---------------------------------------------------------------------------
__global__ void __launch_bounds__(256)
tp_layer_fallback_kernel(const float* __restrict__ x,
                         const float* __restrict__ points,
                         const int*   __restrict__ edge_index,
                         const float* __restrict__ dt_p,
                         const float* __restrict__ dist,
                         const float* __restrict__ weight,
                         float* __restrict__ out,
                         int total)
{
    int gid = blockIdx.x * blockDim.x + threadIdx.x;
    if (gid >= total) return;
    const int b = gid >> 14;
    const int s = gid & (SIZE - 1);

    const float* pts_b = points + (size_t)b * SIZE * 2;
    const float* x_b   = x + (size_t)b * SIZE;
    const float2 pc = *reinterpret_cast<const float2*>(pts_b + 2 * s);
    const float  vc = x_b[s];

    const int4*   ei4 = reinterpret_cast<const int4*>(edge_index + (size_t)b * SIZE * KNN + (size_t)s * KNN);
    const float4* dw4 = reinterpret_cast<const float4*>(dist       + (size_t)b * SIZE * KNN + (size_t)s * KNN);

    Accum A; A.init();
    #pragma unroll
    for (int g = 0; g < 4; ++g) {
        const int4   ei = ei4[g];
        const float4 dw = dw4[g];
        const int   idx[4] = {ei.x, ei.y, ei.z, ei.w};
        const float wts[4] = {dw.x, dw.y, dw.z, dw.w};
        #pragma unroll
        for (int j = 0; j < 4; ++j) {
            const int id = idx[j];
            const float2 pn = *reinterpret_cast<const float2*>(pts_b + 2 * id);
            A.add(pn.x - pc.x, pn.y - pc.y, wts[j], x_b[id] - vc);
        }
    }
    const float du = solve_and_dot(A, weight);
    out[gid] = vc + dt_p[0] * du;
}

extern "C" void kernel_launch(void* const* d_in, const int* in_sizes, int n_in,
                              void* d_out, int out_size)
{
    const float* x      = (const float*)d_in[0];
    const float* points = (const float*)d_in[1];
    const int*   eidx   = (const int*)  d_in[2];
    const float* dt     = (const float*)d_in[3];
    const float* dist   = (const float*)d_in[4];
    const float* weight = (const float*)d_in[5];
    float* out = (float*)d_out;

    // Opt-in smem; environment-deterministic (same result on every call).
    // Not a stream op -> not part of the captured graph.
    cudaError_t attr_ok = cudaFuncSetAttribute(
        tp_layer_smem_kernel,
        cudaFuncAttributeMaxDynamicSharedMemorySize,
        SMEM_BYTES);

    if (attr_ok == cudaSuccess) {
        tp_layer_smem_kernel<<<NBATCH * CHUNKS, NTHREADS, SMEM_BYTES>>>(
            x, points, eidx, dt, dist, weight, out);
    } else {
        const int total = out_size;
        tp_layer_fallback_kernel<<<(total + 255) / 256, 256>>>(
            x, points, eidx, dt, dist, weight, out, total);
    }
}

// round 5
// speedup vs baseline: 2.2161x; 1.1839x over previous
#include <cuda_runtime.h>
#include <cuda_bf16.h>

// Problem constants (match reference)
#define SIZE     16384      // 128*128 points per batch
#define KNN      16
#define ND       5          // num derivatives (order 2, 2D)
#define NBATCH   32
#define CHUNKS   4          // CTAs per batch -> grid 128 (single wave on 148 SMs)
#define CTA_PTS  (SIZE / CHUNKS)   // 4096 points per CTA
#define NTHREADS 1024
#define PTS_PER_THREAD (CTA_PTS / NTHREADS)  // 4

// Dynamic smem: float2 pxy[SIZE] (128KB, LDS.64 gathers) + float sv[SIZE] (64KB)
#define SMEM_BYTES (SIZE * sizeof(float2) + SIZE * sizeof(float))  // 196608

__device__ __forceinline__ float frcp_fast(float x) {
    float r;
    asm("rcp.approx.f32 %0, %1;" : "=f"(r) : "f"(x));
    return r;
}

// ---------------------------------------------------------------------------
// Normal-equation accumulator + 5x5 SPD solve
// ---------------------------------------------------------------------------
struct Accum {
    float s00,s01,s02,s03,s04, s11,s12,s13,s14, s22,s23,s24, s33,s34, s44;
    float t0,t1,t2,t3,t4;
    __device__ __forceinline__ void init() {
        s00=s01=s02=s03=s04=s11=s12=s13=s14=s22=s23=s24=s33=s34=s44=0.f;
        t0=t1=t2=t3=t4=0.f;
    }
    __device__ __forceinline__ void add(float dx, float dy, float w, float r0) {
        const float a0 = dx * w;
        const float a1 = dy * w;
        const float a2 = 0.5f * dx * dx * w;
        const float a3 = dx * dy * w;
        const float a4 = 0.5f * dy * dy * w;
        const float r  = r0 * w;
        s00 += a0*a0; s01 += a0*a1; s02 += a0*a2; s03 += a0*a3; s04 += a0*a4;
                      s11 += a1*a1; s12 += a1*a2; s13 += a1*a3; s14 += a1*a4;
                                    s22 += a2*a2; s23 += a2*a3; s24 += a2*a4;
                                                  s33 += a3*a3; s34 += a3*a4;
                                                                s44 += a4*a4;
        t0 += a0*r; t1 += a1*r; t2 += a2*r; t3 += a3*r; t4 += a4*r;
    }
};

__device__ __forceinline__ float solve_and_dot(const Accum& A,
                                               const float* __restrict__ weight)
{
    const float RIDGE = 1e-6f;
    float m[ND][ND];
    m[0][0]=A.s00+RIDGE; m[0][1]=A.s01; m[0][2]=A.s02; m[0][3]=A.s03; m[0][4]=A.s04;
    m[1][0]=A.s01; m[1][1]=A.s11+RIDGE; m[1][2]=A.s12; m[1][3]=A.s13; m[1][4]=A.s14;
    m[2][0]=A.s02; m[2][1]=A.s12; m[2][2]=A.s22+RIDGE; m[2][3]=A.s23; m[2][4]=A.s24;
    m[3][0]=A.s03; m[3][1]=A.s13; m[3][2]=A.s23; m[3][3]=A.s33+RIDGE; m[3][4]=A.s34;
    m[4][0]=A.s04; m[4][1]=A.s14; m[4][2]=A.s24; m[4][3]=A.s34; m[4][4]=A.s44+RIDGE;
    float bv[ND] = {A.t0, A.t1, A.t2, A.t3, A.t4};

    #pragma unroll
    for (int i = 0; i < ND; ++i) {
        const float inv = frcp_fast(m[i][i]);
        #pragma unroll
        for (int r2 = 0; r2 < ND; ++r2) {
            if (r2 > i) {
                const float f = m[r2][i] * inv;
                #pragma unroll
                for (int c = 0; c < ND; ++c)
                    if (c >= i) m[r2][c] -= f * m[i][c];
                bv[r2] -= f * bv[i];
            }
        }
    }
    float sol[ND];
    #pragma unroll
    for (int i = ND - 1; i >= 0; --i) {
        float acc = bv[i];
        #pragma unroll
        for (int c = 0; c < ND; ++c)
            if (c > i) acc -= m[i][c] * sol[c];
        sol[i] = acc * frcp_fast(m[i][i]);
    }
    return sol[0]*weight[0] + sol[1]*weight[1] + sol[2]*weight[2]
         + sol[3]*weight[3] + sol[4]*weight[4];
}

// ---------------------------------------------------------------------------
// Primary kernel: full batch in 192 KB smem; LDS.64 point gathers; single wave
// ---------------------------------------------------------------------------
__global__ void __launch_bounds__(NTHREADS, 1)
tp_layer_smem_kernel(const float* __restrict__ x,
                     const float* __restrict__ points,
                     const int*   __restrict__ edge_index,
                     const float* __restrict__ dt_p,
                     const float* __restrict__ dist,
                     const float* __restrict__ weight,
                     float* __restrict__ out)
{
    extern __shared__ float smem[];
    float2* pxy = reinterpret_cast<float2*>(smem);          // [SIZE]
    float*  sv  = smem + 2 * SIZE;                           // [SIZE]

    const int b     = blockIdx.x / CHUNKS;
    const int chunk = blockIdx.x % CHUNKS;
    const int tid   = threadIdx.x;

    const float* pts_b = points + (size_t)b * SIZE * 2;
    const float* x_b   = x + (size_t)b * SIZE;

    // Stage: points are (x,y)-interleaved in global, same layout as pxy ->
    // straight coalesced float4 copies for both arrays.
    {
        float4* dstp = reinterpret_cast<float4*>(pxy);
        const float4* srcp = reinterpret_cast<const float4*>(pts_b);
        #pragma unroll
        for (int i = 0; i < (SIZE * 2 / 4) / NTHREADS; ++i)   // 8 iters
            dstp[tid + i * NTHREADS] = srcp[tid + i * NTHREADS];

        float4* dstx = reinterpret_cast<float4*>(sv);
        const float4* srcx = reinterpret_cast<const float4*>(x_b);
        #pragma unroll
        for (int i = 0; i < (SIZE / 4) / NTHREADS; ++i)       // 4 iters
            dstx[tid + i * NTHREADS] = srcx[tid + i * NTHREADS];
    }
    __syncthreads();

    const float dt = dt_p[0];
    const int s_base = chunk * CTA_PTS;
    const int*   eidx_g = edge_index + (size_t)b * SIZE * KNN;
    const float* dist_g = dist       + (size_t)b * SIZE * KNN;

    #pragma unroll 1    // keep body size/regs bounded; inner loops fully unrolled
    for (int p = 0; p < PTS_PER_THREAD; ++p) {
        const int s = s_base + tid + p * NTHREADS;

        const float2 pc = pxy[s];
        const float  vc = sv[s];
        const int4*   ei4 = reinterpret_cast<const int4*>(eidx_g + (size_t)s * KNN);
        const float4* dw4 = reinterpret_cast<const float4*>(dist_g + (size_t)s * KNN);

        Accum A; A.init();
        #pragma unroll
        for (int g = 0; g < 4; ++g) {
            const int4   ei = ei4[g];
            const float4 dw = dw4[g];
            const int   idx[4] = {ei.x, ei.y, ei.z, ei.w};
            const float wts[4] = {dw.x, dw.y, dw.z, dw.w};
            #pragma unroll
            for (int j = 0; j < 4; ++j) {
                const int id = idx[j];
                const float2 pn = pxy[id];          // LDS.64
                const float  vn = sv[id];           // LDS.32
                A.add(pn.x - pc.x, pn.y - pc.y, wts[j], vn - vc);
            }
        }
        const float du = solve_and_dot(A, weight);
        out[(size_t)b * SIZE + s] = vc + dt * du;
    }
}

// ---------------------------------------------------------------------------
// Fallback kernel (global-memory gathers, no opt-in smem) — env insurance only
// ---------------------------------------------------------------------------
__global__ void __launch_bounds__(256)
tp_layer_fallback_kernel(const float* __restrict__ x,
                         const float* __restrict__ points,
                         const int*   __restrict__ edge_index,
                         const float* __restrict__ dt_p,
                         const float* __restrict__ dist,
                         const float* __restrict__ weight,
                         float* __restrict__ out,
                         int total)
{
    int gid = blockIdx.x * blockDim.x + threadIdx.x;
    if (gid >= total) return;
    const int b = gid >> 14;
    const int s = gid & (SIZE - 1);

    const float* pts_b = points + (size_t)b * SIZE * 2;
    const float* x_b   = x + (size_t)b * SIZE;
    const float2 pc = *reinterpret_cast<const float2*>(pts_b + 2 * s);
    const float  vc = x_b[s];

    const int4*   ei4 = reinterpret_cast<const int4*>(edge_index + (size_t)b * SIZE * KNN + (size_t)s * KNN);
    const float4* dw4 = reinterpret_cast<const float4*>(dist       + (size_t)b * SIZE * KNN + (size_t)s * KNN);

    Accum A; A.init();
    #pragma unroll
    for (int g = 0; g < 4; ++g) {
        const int4   ei = ei4[g];
        const float4 dw = dw4[g];
        const int   idx[4] = {ei.x, ei.y, ei.z, ei.w};
        const float wts[4] = {dw.x, dw.y, dw.z, dw.w};
        #pragma unroll
        for (int j = 0; j < 4; ++j) {
            const int id = idx[j];
            const float2 pn = *reinterpret_cast<const float2*>(pts_b + 2 * id);
            A.add(pn.x - pc.x, pn.y - pc.y, wts[j], x_b[id] - vc);
        }
    }
    const float du = solve_and_dot(A, weight);
    out[gid] = vc + dt_p[0] * du;
}

extern "C" void kernel_launch(void* const* d_in, const int* in_sizes, int n_in,
                              void* d_out, int out_size)
{
    const float* x      = (const float*)d_in[0];
    const float* points = (const float*)d_in[1];
    const int*   eidx   = (const int*)  d_in[2];
    const float* dt     = (const float*)d_in[3];
    const float* dist   = (const float*)d_in[4];
    const float* weight = (const float*)d_in[5];
    float* out = (float*)d_out;

    // Opt-in smem; environment-deterministic, identical on every call.
    // Not a stream op -> not part of the captured graph.
    cudaError_t attr_ok = cudaFuncSetAttribute(
        tp_layer_smem_kernel,
        cudaFuncAttributeMaxDynamicSharedMemorySize,
        SMEM_BYTES);

    if (attr_ok == cudaSuccess) {
        tp_layer_smem_kernel<<<NBATCH * CHUNKS, NTHREADS, SMEM_BYTES>>>(
            x, points, eidx, dt, dist, weight, out);
    } else {
        const int total = out_size;
        tp_layer_fallback_kernel<<<(total + 255) / 256, 256>>>(
            x, points, eidx, dt, dist, weight, out, total);
    }
}